// round 8
// baseline (speedup 1.0000x reference)
#include <cuda_runtime.h>
#include <cuda_bf16.h>
#include <cstdint>

// GAT: B=4, N=4096, C=64
// out = elu( softmax_j( mask(adj>0.5, lrelu(s1+s2)) ) @ h )
// R7: adj read direct from gmem (L2-resident), one __syncthreads per tile,
//     32KB stages (h-tiles only), CP_WAIT after phase B.

#define GB 4
#define GN 4096
#define GC 64
#define TI 64
#define TJ 64
#define NTILES (GN / TJ)
#define ALPHA 0.2f
#define THRESH 0.5f

// per-stage smem layout
#define WH_OFF  0         // 64 rows x 128B bf16    ( 8 KB)
#define WL_OFF  8192      // 64 rows x 128B bf16    ( 8 KB)
#define BH_OFF  16384     // 64 rows x 128B bf16    ( 8 KB)
#define BL_OFF  24576     // 64 rows x 128B bf16    ( 8 KB)
#define STAGE   32768
#define DSMEM_BYTES (2 * STAGE + 1024)

__device__ float g_s1[GB * GN];
__device__ float g_s2[GB * GN];
__device__ __nv_bfloat16 g_hh[GB * GN * GC];
__device__ __nv_bfloat16 g_hl[GB * GN * GC];

// ---------------------------------------------------------------- helpers
static __device__ __forceinline__ uint32_t smem_u32(const void* p) {
    uint32_t a;
    asm("{ .reg .u64 t; cvta.to.shared.u64 t, %1; cvt.u32.u64 %0, t; }"
        : "=r"(a) : "l"(p));
    return a;
}
static __device__ __forceinline__ float fast_ex2(float x) {
    float r; asm("ex2.approx.f32 %0, %1;" : "=f"(r) : "f"(x)); return r;
}
// packs {lo -> low16, hi -> high16}
static __device__ __forceinline__ uint32_t cvt_bf16x2(float lo, float hi) {
    uint32_t r;
    asm("cvt.rn.bf16x2.f32 %0, %1, %2;" : "=r"(r) : "f"(hi), "f"(lo));
    return r;
}
static __device__ __forceinline__ uint32_t sw128(uint32_t b) {
    return b ^ ((b >> 3) & 0x70);
}
#define CP16(dst, src) \
    asm volatile("cp.async.cg.shared.global [%0], [%1], 16;" \
                 :: "r"(dst), "l"(src) : "memory")
#define CP_COMMIT() asm volatile("cp.async.commit_group;" ::: "memory")
#define CP_WAIT0()  asm volatile("cp.async.wait_group 0;" ::: "memory")

static __device__ __forceinline__ void ldmx4(uint32_t* r, uint32_t addr) {
    asm volatile("ldmatrix.sync.aligned.m8n8.x4.shared.b16 {%0,%1,%2,%3}, [%4];"
        : "=r"(r[0]), "=r"(r[1]), "=r"(r[2]), "=r"(r[3]) : "r"(addr));
}
static __device__ __forceinline__ void ldmx4t(uint32_t* r, uint32_t addr) {
    asm volatile("ldmatrix.sync.aligned.m8n8.x4.trans.shared.b16 {%0,%1,%2,%3}, [%4];"
        : "=r"(r[0]), "=r"(r[1]), "=r"(r[2]), "=r"(r[3]) : "r"(addr));
}
static __device__ __forceinline__ void mma_bf16(float* d, const uint32_t* a,
                                                uint32_t b0, uint32_t b1) {
    asm volatile(
        "mma.sync.aligned.m16n8k16.row.col.f32.bf16.bf16.f32 "
        "{%0,%1,%2,%3}, {%4,%5,%6,%7}, {%8,%9}, {%0,%1,%2,%3};"
        : "+f"(d[0]), "+f"(d[1]), "+f"(d[2]), "+f"(d[3])
        : "r"(a[0]), "r"(a[1]), "r"(a[2]), "r"(a[3]), "r"(b0), "r"(b1));
}

// ---------------------------------------------------------------- kernel 1
__global__ void gat_scores_kernel(const float* __restrict__ h,
                                  const float* __restrict__ a) {
    int warp = (blockIdx.x * blockDim.x + threadIdx.x) >> 5;
    int lane = threadIdx.x & 31;
    if (warp >= GB * GN) return;
    const float* row = h + (size_t)warp * GC;
    float v0 = row[lane];
    float v1 = row[lane + 32];

    __nv_bfloat16 h0 = __float2bfloat16_rn(v0);
    __nv_bfloat16 h1 = __float2bfloat16_rn(v1);
    g_hh[warp * GC + lane]      = h0;
    g_hh[warp * GC + lane + 32] = h1;
    g_hl[warp * GC + lane]      = __float2bfloat16_rn(v0 - __bfloat162float(h0));
    g_hl[warp * GC + lane + 32] = __float2bfloat16_rn(v1 - __bfloat162float(h1));

    float p1 = v0 * a[lane]      + v1 * a[lane + 32];
    float p2 = v0 * a[GC + lane] + v1 * a[GC + lane + 32];
#pragma unroll
    for (int o = 16; o; o >>= 1) {
        p1 += __shfl_xor_sync(0xFFFFFFFFu, p1, o);
        p2 += __shfl_xor_sync(0xFFFFFFFFu, p2, o);
    }
    const float LOG2E = 1.4426950408889634f;
    if (lane == 0) {
        g_s1[warp] = p1 * LOG2E;
        g_s2[warp] = p2 * LOG2E;
    }
}

// ---------------------------------------------------------------- prefetch
// h hi/lo tiles only: 64 x 64 bf16 each, K-major SW128.
static __device__ __forceinline__ void prefetch_tile(uint32_t stg,
                                                     int b, int j0, int t) {
    const __nv_bfloat16* hh = g_hh + ((size_t)b * GN + j0) * GC;
    const __nv_bfloat16* hl = g_hl + ((size_t)b * GN + j0) * GC;
#pragma unroll
    for (int k = 0; k < 2; k++) {
        int q = t + 256 * k;
        int j = q >> 3, cc = q & 7;
        uint32_t off = sw128((uint32_t)(j * 128 + cc * 16));
        CP16(stg + BH_OFF + off, hh + j * GC + cc * 8);
        CP16(stg + BL_OFF + off, hl + j * GC + cc * 8);
    }
}

// ---------------------------------------------------------------- kernel 2
__global__ __launch_bounds__(256, 2)
void gat_main_kernel(const float* __restrict__ adj,
                     float* __restrict__ out) {
    extern __shared__ char smem_raw[];
    __shared__ float sh_l[TI];

    const int t    = threadIdx.x;
    const int wid  = t >> 5;
    const int lane = t & 31;
    const int b    = blockIdx.y;
    const int i0   = blockIdx.x * TI;
    const int wm   = wid & 3;    // M group: rows wm*16 .. +15
    const int wn   = wid >> 2;   // N group: cols wn*32 .. +31

    uint32_t raw_u32 = smem_u32(smem_raw);
    uint32_t sbu = (raw_u32 + 1023u) & ~1023u;

    if (t < TI) sh_l[t] = 0.0f;

    // phase-B mapping: rows r0 + 16k (k<4), cols jj0..+3
    const int r0  = t >> 4;
    const int jj0 = (t & 15) * 4;
    float s1r[4];
#pragma unroll
    for (int k = 0; k < 4; k++)
        s1r[k] = g_s1[b * GN + i0 + r0 + 16 * k];
    float lsum[4] = {0.f, 0.f, 0.f, 0.f};

    // adj base for this thread (rows r0+16k, cols jj0..+3 of the tile)
    const float* adjp = adj + (size_t)(i0 + r0) * GN + jj0;

    // ldmatrix per-lane constants
    const uint32_t xr     = (uint32_t)(lane & 7) << 4;
    const uint32_t a_base = (uint32_t)((wm * 16 + (lane & 15)) * 128 + (lane & 16));
    const uint32_t b_base = (uint32_t)((lane & 15) * 128 + (lane & 16) + wn * 64);

    float acc[4][4];
#pragma unroll
    for (int nn = 0; nn < 4; nn++)
#pragma unroll
        for (int q = 0; q < 4; q++) acc[nn][q] = 0.0f;

    // prologue: prefetch h-tiles of tile 0 into stage 0
    prefetch_tile(sbu, b, 0, t);
    CP_COMMIT();

    for (int tile = 0; tile < NTILES; tile++) {
        const int s = tile & 1;
        const uint32_t stg = sbu + s * STAGE;
        const int j0 = tile * TJ;

        // ---- phase B: w tile (hi/lo bf16, K-major, SW128), adj from gmem ----
        {
            float4 s2v = *(const float4*)&g_s2[b * GN + j0 + jj0];
            const float* ap = adjp + j0;
            float4 av[4];
#pragma unroll
            for (int k = 0; k < 4; k++)
                av[k] = __ldg((const float4*)(ap + (size_t)(16 * k) * GN));
            uint32_t wbase = sw128((uint32_t)(r0 * 128 + jj0 * 2));
#pragma unroll
            for (int k = 0; k < 4; k++) {
                float e0 = s1r[k] + s2v.x; e0 = fmaxf(e0, ALPHA * e0);
                float e1 = s1r[k] + s2v.y; e1 = fmaxf(e1, ALPHA * e1);
                float e2 = s1r[k] + s2v.z; e2 = fmaxf(e2, ALPHA * e2);
                float e3 = s1r[k] + s2v.w; e3 = fmaxf(e3, ALPHA * e3);
                float w0 = (av[k].x > THRESH) ? fast_ex2(e0) : 0.0f;
                float w1 = (av[k].y > THRESH) ? fast_ex2(e1) : 0.0f;
                float w2 = (av[k].z > THRESH) ? fast_ex2(e2) : 0.0f;
                float w3 = (av[k].w > THRESH) ? fast_ex2(e3) : 0.0f;
                lsum[k] += (w0 + w1) + (w2 + w3);
                uint32_t h01 = cvt_bf16x2(w0, w1);
                uint32_t h23 = cvt_bf16x2(w2, w3);
                float f0 = __uint_as_float(h01 << 16);
                float f1 = __uint_as_float(h01 & 0xFFFF0000u);
                float f2 = __uint_as_float(h23 << 16);
                float f3 = __uint_as_float(h23 & 0xFFFF0000u);
                uint32_t l01 = cvt_bf16x2(w0 - f0, w1 - f1);
                uint32_t l23 = cvt_bf16x2(w2 - f2, w3 - f3);
                asm volatile("st.shared.v2.b32 [%0], {%1,%2};"
                             :: "r"(stg + WH_OFF + wbase + k * 2048),
                                "r"(h01), "r"(h23) : "memory");
                asm volatile("st.shared.v2.b32 [%0], {%1,%2};"
                             :: "r"(stg + WL_OFF + wbase + k * 2048),
                                "r"(l01), "r"(l23) : "memory");
            }
        }

        CP_WAIT0();        // this tile's h-copies (issued last iter) done
        __syncthreads();   // W visible; MMA(t-1) complete in all warps

        // ---- prefetch next tile's h into other stage (overlaps MMA) ----
        if (tile + 1 < NTILES) {
            prefetch_tile(sbu + (s ^ 1) * STAGE, b, j0 + TJ, t);
            CP_COMMIT();
        }

        // ---- MMA phase: 3-term bf16, warp tile 16x32 ----
        {
            const uint32_t whb = stg + WH_OFF;
            const uint32_t wlb = stg + WL_OFF;
            const uint32_t bhb = stg + BH_OFF;
            const uint32_t blb = stg + BL_OFF;
#pragma unroll
            for (int kk = 0; kk < 4; kk++) {
                uint32_t ahi[4], alo[4];
                uint32_t a_off = (a_base + kk * 32) ^ xr;
                ldmx4(ahi, whb + a_off);
                ldmx4(alo, wlb + a_off);
                uint32_t bh[8], bl[8];
#pragma unroll
                for (int np = 0; np < 2; np++) {
                    uint32_t b_off = (b_base + kk * 2048 + np * 32) ^ xr;
                    ldmx4t(&bh[np * 4], bhb + b_off);
                    ldmx4t(&bl[np * 4], blb + b_off);
                }
#pragma unroll
                for (int nn = 0; nn < 4; nn++) {
                    int base = (nn >> 1) * 4 + (nn & 1) * 2;
                    mma_bf16(acc[nn], ahi, bh[base], bh[base + 1]);
                    mma_bf16(acc[nn], ahi, bl[base], bl[base + 1]);
                    mma_bf16(acc[nn], alo, bh[base], bh[base + 1]);
                }
            }
        }
    }

    // ---- row sums ----
#pragma unroll
    for (int k = 0; k < 4; k++)
        atomicAdd(&sh_l[r0 + 16 * k], lsum[k]);
    __syncthreads();

    // ---- epilogue: normalize + ELU + store ----
    {
        int g  = lane >> 2;
        int qc = (lane & 3) * 2;
        int ra = wm * 16 + g;
        int rb = ra + 8;
        float la = 1.0f / sh_l[ra];
        float lb = 1.0f / sh_l[rb];
        float* oa = out + ((size_t)b * GN + i0 + ra) * GC;
        float* ob = out + ((size_t)b * GN + i0 + rb) * GC;
#pragma unroll
        for (int nn = 0; nn < 4; nn++) {
            int c = wn * 32 + nn * 8 + qc;
            float v0 = acc[nn][0] * la, v1 = acc[nn][1] * la;
            float v2 = acc[nn][2] * lb, v3 = acc[nn][3] * lb;
            float2 pa, pb;
            pa.x = (v0 > 0.f) ? v0 : expm1f(v0);
            pa.y = (v1 > 0.f) ? v1 : expm1f(v1);
            pb.x = (v2 > 0.f) ? v2 : expm1f(v2);
            pb.y = (v3 > 0.f) ? v3 : expm1f(v3);
            *(float2*)(oa + c) = pa;
            *(float2*)(ob + c) = pb;
        }
    }
}

// ---------------------------------------------------------------- launch
extern "C" void kernel_launch(void* const* d_in, const int* in_sizes, int n_in,
                              void* d_out, int out_size) {
    const float* input = (const float*)d_in[0];   // (B, N, C)
    const float* adj   = (const float*)d_in[1];   // (N, N)
    const float* a     = (const float*)d_in[2];   // (2C, 1)
    float* out = (float*)d_out;                   // (B, N, C)

    gat_scores_kernel<<<(GB * GN) / 8, 256>>>(input, a);

    cudaFuncSetAttribute(gat_main_kernel,
                         cudaFuncAttributeMaxDynamicSharedMemorySize, DSMEM_BYTES);
    dim3 grid(GN / TI, GB);
    gat_main_kernel<<<grid, 256, DSMEM_BYTES>>>(adj, out);
}

// round 9
// speedup vs baseline: 1.2817x; 1.2817x over previous
#include <cuda_runtime.h>
#include <cuda_bf16.h>
#include <cstdint>

// GAT: B=4, N=4096, C=64
// out = elu( softmax_j( mask(adj>0.5, lrelu(s1+s2)) ) @ h )
// R8: R7 structure (1 sync/tile, h-only cp.async double-buffer) +
//     adj register-prefetch one tile ahead (latency hidden under MMA).

#define GB 4
#define GN 4096
#define GC 64
#define TI 64
#define TJ 64
#define NTILES (GN / TJ)
#define ALPHA 0.2f
#define THRESH 0.5f

// per-stage smem layout
#define WH_OFF  0         // 64 rows x 128B bf16    ( 8 KB)
#define WL_OFF  8192      // 64 rows x 128B bf16    ( 8 KB)
#define BH_OFF  16384     // 64 rows x 128B bf16    ( 8 KB)
#define BL_OFF  24576     // 64 rows x 128B bf16    ( 8 KB)
#define STAGE   32768
#define DSMEM_BYTES (2 * STAGE + 1024)

__device__ float g_s1[GB * GN];
__device__ float g_s2[GB * GN];
__device__ __nv_bfloat16 g_hh[GB * GN * GC];
__device__ __nv_bfloat16 g_hl[GB * GN * GC];

// ---------------------------------------------------------------- helpers
static __device__ __forceinline__ uint32_t smem_u32(const void* p) {
    uint32_t a;
    asm("{ .reg .u64 t; cvta.to.shared.u64 t, %1; cvt.u32.u64 %0, t; }"
        : "=r"(a) : "l"(p));
    return a;
}
static __device__ __forceinline__ float fast_ex2(float x) {
    float r; asm("ex2.approx.f32 %0, %1;" : "=f"(r) : "f"(x)); return r;
}
// packs {lo -> low16, hi -> high16}
static __device__ __forceinline__ uint32_t cvt_bf16x2(float lo, float hi) {
    uint32_t r;
    asm("cvt.rn.bf16x2.f32 %0, %1, %2;" : "=r"(r) : "f"(hi), "f"(lo));
    return r;
}
static __device__ __forceinline__ uint32_t sw128(uint32_t b) {
    return b ^ ((b >> 3) & 0x70);
}
#define CP16(dst, src) \
    asm volatile("cp.async.cg.shared.global [%0], [%1], 16;" \
                 :: "r"(dst), "l"(src) : "memory")
#define CP_COMMIT() asm volatile("cp.async.commit_group;" ::: "memory")
#define CP_WAIT0()  asm volatile("cp.async.wait_group 0;" ::: "memory")

static __device__ __forceinline__ void ldmx4(uint32_t* r, uint32_t addr) {
    asm volatile("ldmatrix.sync.aligned.m8n8.x4.shared.b16 {%0,%1,%2,%3}, [%4];"
        : "=r"(r[0]), "=r"(r[1]), "=r"(r[2]), "=r"(r[3]) : "r"(addr));
}
static __device__ __forceinline__ void ldmx4t(uint32_t* r, uint32_t addr) {
    asm volatile("ldmatrix.sync.aligned.m8n8.x4.trans.shared.b16 {%0,%1,%2,%3}, [%4];"
        : "=r"(r[0]), "=r"(r[1]), "=r"(r[2]), "=r"(r[3]) : "r"(addr));
}
static __device__ __forceinline__ void mma_bf16(float* d, const uint32_t* a,
                                                uint32_t b0, uint32_t b1) {
    asm volatile(
        "mma.sync.aligned.m16n8k16.row.col.f32.bf16.bf16.f32 "
        "{%0,%1,%2,%3}, {%4,%5,%6,%7}, {%8,%9}, {%0,%1,%2,%3};"
        : "+f"(d[0]), "+f"(d[1]), "+f"(d[2]), "+f"(d[3])
        : "r"(a[0]), "r"(a[1]), "r"(a[2]), "r"(a[3]), "r"(b0), "r"(b1));
}

// ---------------------------------------------------------------- kernel 1
__global__ void gat_scores_kernel(const float* __restrict__ h,
                                  const float* __restrict__ a) {
    int warp = (blockIdx.x * blockDim.x + threadIdx.x) >> 5;
    int lane = threadIdx.x & 31;
    if (warp >= GB * GN) return;
    const float* row = h + (size_t)warp * GC;
    float v0 = row[lane];
    float v1 = row[lane + 32];

    __nv_bfloat16 h0 = __float2bfloat16_rn(v0);
    __nv_bfloat16 h1 = __float2bfloat16_rn(v1);
    g_hh[warp * GC + lane]      = h0;
    g_hh[warp * GC + lane + 32] = h1;
    g_hl[warp * GC + lane]      = __float2bfloat16_rn(v0 - __bfloat162float(h0));
    g_hl[warp * GC + lane + 32] = __float2bfloat16_rn(v1 - __bfloat162float(h1));

    float p1 = v0 * a[lane]      + v1 * a[lane + 32];
    float p2 = v0 * a[GC + lane] + v1 * a[GC + lane + 32];
#pragma unroll
    for (int o = 16; o; o >>= 1) {
        p1 += __shfl_xor_sync(0xFFFFFFFFu, p1, o);
        p2 += __shfl_xor_sync(0xFFFFFFFFu, p2, o);
    }
    const float LOG2E = 1.4426950408889634f;
    if (lane == 0) {
        g_s1[warp] = p1 * LOG2E;
        g_s2[warp] = p2 * LOG2E;
    }
}

// ---------------------------------------------------------------- prefetch
// h hi/lo tiles only: 64 x 64 bf16 each, K-major SW128.
static __device__ __forceinline__ void prefetch_tile(uint32_t stg,
                                                     int b, int j0, int t) {
    const __nv_bfloat16* hh = g_hh + ((size_t)b * GN + j0) * GC;
    const __nv_bfloat16* hl = g_hl + ((size_t)b * GN + j0) * GC;
#pragma unroll
    for (int k = 0; k < 2; k++) {
        int q = t + 256 * k;
        int j = q >> 3, cc = q & 7;
        uint32_t off = sw128((uint32_t)(j * 128 + cc * 16));
        CP16(stg + BH_OFF + off, hh + j * GC + cc * 8);
        CP16(stg + BL_OFF + off, hl + j * GC + cc * 8);
    }
}

// ---------------------------------------------------------------- kernel 2
__global__ __launch_bounds__(256, 2)
void gat_main_kernel(const float* __restrict__ adj,
                     float* __restrict__ out) {
    extern __shared__ char smem_raw[];
    __shared__ float sh_l[TI];

    const int t    = threadIdx.x;
    const int wid  = t >> 5;
    const int lane = t & 31;
    const int b    = blockIdx.y;
    const int i0   = blockIdx.x * TI;
    const int wm   = wid & 3;    // M group: rows wm*16 .. +15
    const int wn   = wid >> 2;   // N group: cols wn*32 .. +31

    uint32_t raw_u32 = smem_u32(smem_raw);
    uint32_t sbu = (raw_u32 + 1023u) & ~1023u;

    if (t < TI) sh_l[t] = 0.0f;

    // phase-B mapping: rows r0 + 16k (k<4), cols jj0..+3
    const int r0  = t >> 4;
    const int jj0 = (t & 15) * 4;
    float s1r[4];
#pragma unroll
    for (int k = 0; k < 4; k++)
        s1r[k] = g_s1[b * GN + i0 + r0 + 16 * k];
    float lsum[4] = {0.f, 0.f, 0.f, 0.f};

    // adj base for this thread (rows r0+16k, cols jj0..+3 of the tile)
    const float* adjp = adj + (size_t)(i0 + r0) * GN + jj0;

    // ldmatrix per-lane constants
    const uint32_t xr     = (uint32_t)(lane & 7) << 4;
    const uint32_t a_base = (uint32_t)((wm * 16 + (lane & 15)) * 128 + (lane & 16));
    const uint32_t b_base = (uint32_t)((lane & 15) * 128 + (lane & 16) + wn * 64);

    float acc[4][4];
#pragma unroll
    for (int nn = 0; nn < 4; nn++)
#pragma unroll
        for (int q = 0; q < 4; q++) acc[nn][q] = 0.0f;

    // prologue: prefetch h-tiles of tile 0 into stage 0; adj tile 0 into regs
    prefetch_tile(sbu, b, 0, t);
    CP_COMMIT();
    float4 av[4];
#pragma unroll
    for (int k = 0; k < 4; k++)
        av[k] = __ldg((const float4*)(adjp + (size_t)(16 * k) * GN));

    for (int tile = 0; tile < NTILES; tile++) {
        const int s = tile & 1;
        const uint32_t stg = sbu + s * STAGE;
        const int j0 = tile * TJ;

        // ---- phase B: w tile (hi/lo bf16, K-major, SW128), adj from regs ----
        {
            float4 s2v = *(const float4*)&g_s2[b * GN + j0 + jj0];
            uint32_t wbase = sw128((uint32_t)(r0 * 128 + jj0 * 2));
#pragma unroll
            for (int k = 0; k < 4; k++) {
                float e0 = s1r[k] + s2v.x; e0 = fmaxf(e0, ALPHA * e0);
                float e1 = s1r[k] + s2v.y; e1 = fmaxf(e1, ALPHA * e1);
                float e2 = s1r[k] + s2v.z; e2 = fmaxf(e2, ALPHA * e2);
                float e3 = s1r[k] + s2v.w; e3 = fmaxf(e3, ALPHA * e3);
                float w0 = (av[k].x > THRESH) ? fast_ex2(e0) : 0.0f;
                float w1 = (av[k].y > THRESH) ? fast_ex2(e1) : 0.0f;
                float w2 = (av[k].z > THRESH) ? fast_ex2(e2) : 0.0f;
                float w3 = (av[k].w > THRESH) ? fast_ex2(e3) : 0.0f;
                lsum[k] += (w0 + w1) + (w2 + w3);
                uint32_t h01 = cvt_bf16x2(w0, w1);
                uint32_t h23 = cvt_bf16x2(w2, w3);
                float f0 = __uint_as_float(h01 << 16);
                float f1 = __uint_as_float(h01 & 0xFFFF0000u);
                float f2 = __uint_as_float(h23 << 16);
                float f3 = __uint_as_float(h23 & 0xFFFF0000u);
                uint32_t l01 = cvt_bf16x2(w0 - f0, w1 - f1);
                uint32_t l23 = cvt_bf16x2(w2 - f2, w3 - f3);
                asm volatile("st.shared.v2.b32 [%0], {%1,%2};"
                             :: "r"(stg + WH_OFF + wbase + k * 2048),
                                "r"(h01), "r"(h23) : "memory");
                asm volatile("st.shared.v2.b32 [%0], {%1,%2};"
                             :: "r"(stg + WL_OFF + wbase + k * 2048),
                                "r"(l01), "r"(l23) : "memory");
            }
        }

        // ---- issue adj loads for NEXT tile (consumed after full MMA phase) ----
        {
            // last iteration re-loads tile 0 (values unused) to keep the
            // instruction stream branch-free and uniform
            int jn = (tile + 1 < NTILES) ? (j0 + TJ) : 0;
            const float* ap = adjp + jn;
#pragma unroll
            for (int k = 0; k < 4; k++)
                av[k] = __ldg((const float4*)(ap + (size_t)(16 * k) * GN));
        }

        CP_WAIT0();        // this tile's h-copies (issued last iter) done
        __syncthreads();   // W visible; MMA(t-1) complete in all warps

        // ---- prefetch next tile's h into other stage (overlaps MMA) ----
        if (tile + 1 < NTILES) {
            prefetch_tile(sbu + (s ^ 1) * STAGE, b, j0 + TJ, t);
            CP_COMMIT();
        }

        // ---- MMA phase: 3-term bf16, warp tile 16x32 ----
        {
            const uint32_t whb = stg + WH_OFF;
            const uint32_t wlb = stg + WL_OFF;
            const uint32_t bhb = stg + BH_OFF;
            const uint32_t blb = stg + BL_OFF;
#pragma unroll
            for (int kk = 0; kk < 4; kk++) {
                uint32_t ahi[4], alo[4];
                uint32_t a_off = (a_base + kk * 32) ^ xr;
                ldmx4(ahi, whb + a_off);
                ldmx4(alo, wlb + a_off);
                uint32_t bh[8], bl[8];
#pragma unroll
                for (int np = 0; np < 2; np++) {
                    uint32_t b_off = (b_base + kk * 2048 + np * 32) ^ xr;
                    ldmx4t(&bh[np * 4], bhb + b_off);
                    ldmx4t(&bl[np * 4], blb + b_off);
                }
#pragma unroll
                for (int nn = 0; nn < 4; nn++) {
                    int base = (nn >> 1) * 4 + (nn & 1) * 2;
                    mma_bf16(acc[nn], ahi, bh[base], bh[base + 1]);
                    mma_bf16(acc[nn], ahi, bl[base], bl[base + 1]);
                    mma_bf16(acc[nn], alo, bh[base], bh[base + 1]);
                }
            }
        }
    }

    // ---- row sums ----
#pragma unroll
    for (int k = 0; k < 4; k++)
        atomicAdd(&sh_l[r0 + 16 * k], lsum[k]);
    __syncthreads();

    // ---- epilogue: normalize + ELU + store ----
    {
        int g  = lane >> 2;
        int qc = (lane & 3) * 2;
        int ra = wm * 16 + g;
        int rb = ra + 8;
        float la = 1.0f / sh_l[ra];
        float lb = 1.0f / sh_l[rb];
        float* oa = out + ((size_t)b * GN + i0 + ra) * GC;
        float* ob = out + ((size_t)b * GN + i0 + rb) * GC;
#pragma unroll
        for (int nn = 0; nn < 4; nn++) {
            int c = wn * 32 + nn * 8 + qc;
            float v0 = acc[nn][0] * la, v1 = acc[nn][1] * la;
            float v2 = acc[nn][2] * lb, v3 = acc[nn][3] * lb;
            float2 pa, pb;
            pa.x = (v0 > 0.f) ? v0 : expm1f(v0);
            pa.y = (v1 > 0.f) ? v1 : expm1f(v1);
            pb.x = (v2 > 0.f) ? v2 : expm1f(v2);
            pb.y = (v3 > 0.f) ? v3 : expm1f(v3);
            *(float2*)(oa + c) = pa;
            *(float2*)(ob + c) = pb;
        }
    }
}

// ---------------------------------------------------------------- launch
extern "C" void kernel_launch(void* const* d_in, const int* in_sizes, int n_in,
                              void* d_out, int out_size) {
    const float* input = (const float*)d_in[0];   // (B, N, C)
    const float* adj   = (const float*)d_in[1];   // (N, N)
    const float* a     = (const float*)d_in[2];   // (2C, 1)
    float* out = (float*)d_out;                   // (B, N, C)

    gat_scores_kernel<<<(GB * GN) / 8, 256>>>(input, a);

    cudaFuncSetAttribute(gat_main_kernel,
                         cudaFuncAttributeMaxDynamicSharedMemorySize, DSMEM_BYTES);
    dim3 grid(GN / TI, GB);
    gat_main_kernel<<<grid, 256, DSMEM_BYTES>>>(adj, out);
}

// round 10
// speedup vs baseline: 1.3016x; 1.0155x over previous
#include <cuda_runtime.h>
#include <cuda_bf16.h>
#include <cstdint>

// GAT: B=4, N=4096, C=64
// out = elu( softmax_j( mask(adj>0.5, lrelu(s1+s2)) ) @ h )
// R10: 3-stage B double... depth-2 cp.async prefetch (wait_group 1),
//      s2 register-prefetch, rolling adj pointers. W double-buffered as before.

#define GB 4
#define GN 4096
#define GC 64
#define TI 64
#define TJ 64
#define NTILES (GN / TJ)
#define ALPHA 0.2f
#define THRESH 0.5f

// smem layout: 3 B-stages then 2 W-stages (all 16 KB, 1024-aligned)
#define BSTG_SZ 16384     // BH 8KB + BL 8KB
#define WSTG_SZ 16384     // WH 8KB + WL 8KB
#define B_HI    0
#define B_LO    8192
#define W_HI    0
#define W_LO    8192
#define W_BASE  (3 * BSTG_SZ)
#define DSMEM_BYTES (3 * BSTG_SZ + 2 * WSTG_SZ + 1024)

__device__ float g_s1[GB * GN];
__device__ float g_s2[GB * GN];
__device__ __nv_bfloat16 g_hh[GB * GN * GC];
__device__ __nv_bfloat16 g_hl[GB * GN * GC];

// ---------------------------------------------------------------- helpers
static __device__ __forceinline__ uint32_t smem_u32(const void* p) {
    uint32_t a;
    asm("{ .reg .u64 t; cvta.to.shared.u64 t, %1; cvt.u32.u64 %0, t; }"
        : "=r"(a) : "l"(p));
    return a;
}
static __device__ __forceinline__ float fast_ex2(float x) {
    float r; asm("ex2.approx.f32 %0, %1;" : "=f"(r) : "f"(x)); return r;
}
// packs {lo -> low16, hi -> high16}
static __device__ __forceinline__ uint32_t cvt_bf16x2(float lo, float hi) {
    uint32_t r;
    asm("cvt.rn.bf16x2.f32 %0, %1, %2;" : "=r"(r) : "f"(hi), "f"(lo));
    return r;
}
static __device__ __forceinline__ uint32_t sw128(uint32_t b) {
    return b ^ ((b >> 3) & 0x70);
}
#define CP16(dst, src) \
    asm volatile("cp.async.cg.shared.global [%0], [%1], 16;" \
                 :: "r"(dst), "l"(src) : "memory")
#define CP_COMMIT() asm volatile("cp.async.commit_group;" ::: "memory")
#define CP_WAIT1()  asm volatile("cp.async.wait_group 1;" ::: "memory")

static __device__ __forceinline__ void ldmx4(uint32_t* r, uint32_t addr) {
    asm volatile("ldmatrix.sync.aligned.m8n8.x4.shared.b16 {%0,%1,%2,%3}, [%4];"
        : "=r"(r[0]), "=r"(r[1]), "=r"(r[2]), "=r"(r[3]) : "r"(addr));
}
static __device__ __forceinline__ void ldmx4t(uint32_t* r, uint32_t addr) {
    asm volatile("ldmatrix.sync.aligned.m8n8.x4.trans.shared.b16 {%0,%1,%2,%3}, [%4];"
        : "=r"(r[0]), "=r"(r[1]), "=r"(r[2]), "=r"(r[3]) : "r"(addr));
}
static __device__ __forceinline__ void mma_bf16(float* d, const uint32_t* a,
                                                uint32_t b0, uint32_t b1) {
    asm volatile(
        "mma.sync.aligned.m16n8k16.row.col.f32.bf16.bf16.f32 "
        "{%0,%1,%2,%3}, {%4,%5,%6,%7}, {%8,%9}, {%0,%1,%2,%3};"
        : "+f"(d[0]), "+f"(d[1]), "+f"(d[2]), "+f"(d[3])
        : "r"(a[0]), "r"(a[1]), "r"(a[2]), "r"(a[3]), "r"(b0), "r"(b1));
}

// ---------------------------------------------------------------- kernel 1
__global__ void gat_scores_kernel(const float* __restrict__ h,
                                  const float* __restrict__ a) {
    int warp = (blockIdx.x * blockDim.x + threadIdx.x) >> 5;
    int lane = threadIdx.x & 31;
    if (warp >= GB * GN) return;
    const float* row = h + (size_t)warp * GC;
    float v0 = row[lane];
    float v1 = row[lane + 32];

    __nv_bfloat16 h0 = __float2bfloat16_rn(v0);
    __nv_bfloat16 h1 = __float2bfloat16_rn(v1);
    g_hh[warp * GC + lane]      = h0;
    g_hh[warp * GC + lane + 32] = h1;
    g_hl[warp * GC + lane]      = __float2bfloat16_rn(v0 - __bfloat162float(h0));
    g_hl[warp * GC + lane + 32] = __float2bfloat16_rn(v1 - __bfloat162float(h1));

    float p1 = v0 * a[lane]      + v1 * a[lane + 32];
    float p2 = v0 * a[GC + lane] + v1 * a[GC + lane + 32];
#pragma unroll
    for (int o = 16; o; o >>= 1) {
        p1 += __shfl_xor_sync(0xFFFFFFFFu, p1, o);
        p2 += __shfl_xor_sync(0xFFFFFFFFu, p2, o);
    }
    const float LOG2E = 1.4426950408889634f;
    if (lane == 0) {
        g_s1[warp] = p1 * LOG2E;
        g_s2[warp] = p2 * LOG2E;
    }
}

// ---------------------------------------------------------------- prefetch
// h hi/lo tiles: 64 x 64 bf16 each, K-major SW128, into B-stage bstg.
static __device__ __forceinline__ void prefetch_tile(uint32_t bstg,
                                                     int b, int j0, int t) {
    const __nv_bfloat16* hh = g_hh + ((size_t)b * GN + j0) * GC;
    const __nv_bfloat16* hl = g_hl + ((size_t)b * GN + j0) * GC;
#pragma unroll
    for (int k = 0; k < 2; k++) {
        int q = t + 256 * k;
        int j = q >> 3, cc = q & 7;
        uint32_t off = sw128((uint32_t)(j * 128 + cc * 16));
        CP16(bstg + B_HI + off, hh + j * GC + cc * 8);
        CP16(bstg + B_LO + off, hl + j * GC + cc * 8);
    }
}

// ---------------------------------------------------------------- kernel 2
__global__ __launch_bounds__(256, 2)
void gat_main_kernel(const float* __restrict__ adj,
                     float* __restrict__ out) {
    extern __shared__ char smem_raw[];
    __shared__ float sh_l[TI];

    const int t    = threadIdx.x;
    const int wid  = t >> 5;
    const int lane = t & 31;
    const int b    = blockIdx.y;
    const int i0   = blockIdx.x * TI;
    const int wm   = wid & 3;    // M group: rows wm*16 .. +15
    const int wn   = wid >> 2;   // N group: cols wn*32 .. +31

    uint32_t raw_u32 = smem_u32(smem_raw);
    uint32_t sbu = (raw_u32 + 1023u) & ~1023u;

    if (t < TI) sh_l[t] = 0.0f;

    // phase-B mapping: rows r0 + 16k (k<4), cols jj0..+3
    const int r0  = t >> 4;
    const int jj0 = (t & 15) * 4;
    float s1r[4];
#pragma unroll
    for (int k = 0; k < 4; k++)
        s1r[k] = g_s1[b * GN + i0 + r0 + 16 * k];
    float lsum[4] = {0.f, 0.f, 0.f, 0.f};

    // rolling adj pointers (one per 16-row group)
    const float* ap0 = adj + (size_t)(i0 + r0)      * GN + jj0;
    const float* ap1 = ap0 + (size_t)16 * GN;
    const float* ap2 = ap0 + (size_t)32 * GN;
    const float* ap3 = ap0 + (size_t)48 * GN;
    const float* s2p = g_s2 + b * GN + jj0;

    // ldmatrix per-lane constants
    const uint32_t xr     = (uint32_t)(lane & 7) << 4;
    const uint32_t a_base = (uint32_t)((wm * 16 + (lane & 15)) * 128 + (lane & 16));
    const uint32_t b_base = (uint32_t)((lane & 15) * 128 + (lane & 16) + wn * 64);

    float acc[4][4];
#pragma unroll
    for (int nn = 0; nn < 4; nn++)
#pragma unroll
        for (int q = 0; q < 4; q++) acc[nn][q] = 0.0f;

    // prologue: B(0) and B(1) prefetch (depth 2); adj(0)+s2(0) into regs
    prefetch_tile(sbu + 0 * BSTG_SZ, b, 0, t);
    CP_COMMIT();
    prefetch_tile(sbu + 1 * BSTG_SZ, b, TJ, t);
    CP_COMMIT();
    float4 av[4];
    av[0] = __ldg((const float4*)ap0);
    av[1] = __ldg((const float4*)ap1);
    av[2] = __ldg((const float4*)ap2);
    av[3] = __ldg((const float4*)ap3);
    float4 s2v = __ldg((const float4*)s2p);

    int bs = 0;    // B stage of current tile (t % 3)
    for (int tile = 0; tile < NTILES; tile++) {
        const int s = tile & 1;
        const uint32_t wstg = sbu + W_BASE + s * WSTG_SZ;
        const uint32_t bstg = sbu + bs * BSTG_SZ;

        // ---- phase B: w tile (hi/lo bf16, K-major, SW128) from regs ----
        {
            uint32_t wbase = sw128((uint32_t)(r0 * 128 + jj0 * 2));
#pragma unroll
            for (int k = 0; k < 4; k++) {
                float e0 = s1r[k] + s2v.x; e0 = fmaxf(e0, ALPHA * e0);
                float e1 = s1r[k] + s2v.y; e1 = fmaxf(e1, ALPHA * e1);
                float e2 = s1r[k] + s2v.z; e2 = fmaxf(e2, ALPHA * e2);
                float e3 = s1r[k] + s2v.w; e3 = fmaxf(e3, ALPHA * e3);
                float w0 = (av[k].x > THRESH) ? fast_ex2(e0) : 0.0f;
                float w1 = (av[k].y > THRESH) ? fast_ex2(e1) : 0.0f;
                float w2 = (av[k].z > THRESH) ? fast_ex2(e2) : 0.0f;
                float w3 = (av[k].w > THRESH) ? fast_ex2(e3) : 0.0f;
                lsum[k] += (w0 + w1) + (w2 + w3);
                uint32_t h01 = cvt_bf16x2(w0, w1);
                uint32_t h23 = cvt_bf16x2(w2, w3);
                float f0 = __uint_as_float(h01 << 16);
                float f1 = __uint_as_float(h01 & 0xFFFF0000u);
                float f2 = __uint_as_float(h23 << 16);
                float f3 = __uint_as_float(h23 & 0xFFFF0000u);
                uint32_t l01 = cvt_bf16x2(w0 - f0, w1 - f1);
                uint32_t l23 = cvt_bf16x2(w2 - f2, w3 - f3);
                asm volatile("st.shared.v2.b32 [%0], {%1,%2};"
                             :: "r"(wstg + W_HI + wbase + k * 2048),
                                "r"(h01), "r"(h23) : "memory");
                asm volatile("st.shared.v2.b32 [%0], {%1,%2};"
                             :: "r"(wstg + W_LO + wbase + k * 2048),
                                "r"(l01), "r"(l23) : "memory");
            }
        }

        // ---- issue adj + s2 loads for NEXT tile (hidden under MMA) ----
        {
            int jn = (tile + 1 < NTILES) ? (tile + 1) * TJ : 0;
            av[0] = __ldg((const float4*)(ap0 + jn));
            av[1] = __ldg((const float4*)(ap1 + jn));
            av[2] = __ldg((const float4*)(ap2 + jn));
            av[3] = __ldg((const float4*)(ap3 + jn));
            s2v   = __ldg((const float4*)(s2p + jn));
        }

        CP_WAIT1();        // B(tile) done (B(tile+1) may remain in flight)
        __syncthreads();   // W + B visible; all warps past mma(tile-1)

        // ---- prefetch B(tile+2) into the stage freed by mma(tile-1) ----
        if (tile + 2 < NTILES) {
            int bs2 = bs + 2; if (bs2 >= 3) bs2 -= 3;
            prefetch_tile(sbu + bs2 * BSTG_SZ, b, (tile + 2) * TJ, t);
        }
        CP_COMMIT();

        // ---- MMA phase: 3-term bf16, warp tile 16x32 ----
        {
            const uint32_t whb = wstg + W_HI;
            const uint32_t wlb = wstg + W_LO;
            const uint32_t bhb = bstg + B_HI;
            const uint32_t blb = bstg + B_LO;
#pragma unroll
            for (int kk = 0; kk < 4; kk++) {
                uint32_t ahi[4], alo[4];
                uint32_t a_off = (a_base + kk * 32) ^ xr;
                ldmx4(ahi, whb + a_off);
                ldmx4(alo, wlb + a_off);
                uint32_t bh[8], bl[8];
#pragma unroll
                for (int np = 0; np < 2; np++) {
                    uint32_t b_off = (b_base + kk * 2048 + np * 32) ^ xr;
                    ldmx4t(&bh[np * 4], bhb + b_off);
                    ldmx4t(&bl[np * 4], blb + b_off);
                }
#pragma unroll
                for (int nn = 0; nn < 4; nn++) {
                    int base = (nn >> 1) * 4 + (nn & 1) * 2;
                    mma_bf16(acc[nn], ahi, bh[base], bh[base + 1]);
                    mma_bf16(acc[nn], ahi, bl[base], bl[base + 1]);
                    mma_bf16(acc[nn], alo, bh[base], bh[base + 1]);
                }
            }
        }

        bs = (bs == 2) ? 0 : bs + 1;
    }

    // ---- row sums ----
#pragma unroll
    for (int k = 0; k < 4; k++)
        atomicAdd(&sh_l[r0 + 16 * k], lsum[k]);
    __syncthreads();

    // ---- epilogue: normalize + ELU + store ----
    {
        int g  = lane >> 2;
        int qc = (lane & 3) * 2;
        int ra = wm * 16 + g;
        int rb = ra + 8;
        float la = 1.0f / sh_l[ra];
        float lb = 1.0f / sh_l[rb];
        float* oa = out + ((size_t)b * GN + i0 + ra) * GC;
        float* ob = out + ((size_t)b * GN + i0 + rb) * GC;
#pragma unroll
        for (int nn = 0; nn < 4; nn++) {
            int c = wn * 32 + nn * 8 + qc;
            float v0 = acc[nn][0] * la, v1 = acc[nn][1] * la;
            float v2 = acc[nn][2] * lb, v3 = acc[nn][3] * lb;
            float2 pa, pb;
            pa.x = (v0 > 0.f) ? v0 : expm1f(v0);
            pa.y = (v1 > 0.f) ? v1 : expm1f(v1);
            pb.x = (v2 > 0.f) ? v2 : expm1f(v2);
            pb.y = (v3 > 0.f) ? v3 : expm1f(v3);
            *(float2*)(oa + c) = pa;
            *(float2*)(ob + c) = pb;
        }
    }
}

// ---------------------------------------------------------------- launch
extern "C" void kernel_launch(void* const* d_in, const int* in_sizes, int n_in,
                              void* d_out, int out_size) {
    const float* input = (const float*)d_in[0];   // (B, N, C)
    const float* adj   = (const float*)d_in[1];   // (N, N)
    const float* a     = (const float*)d_in[2];   // (2C, 1)
    float* out = (float*)d_out;                   // (B, N, C)

    gat_scores_kernel<<<(GB * GN) / 8, 256>>>(input, a);

    cudaFuncSetAttribute(gat_main_kernel,
                         cudaFuncAttributeMaxDynamicSharedMemorySize, DSMEM_BYTES);
    dim3 grid(GN / TI, GB);
    gat_main_kernel<<<grid, 256, DSMEM_BYTES>>>(adj, out);
}